// round 15
// baseline (speedup 1.0000x reference)
#include <cuda_runtime.h>

// IntentGCN fused kernel, GB300 (sm_103a). R14 design (2nd submit; infra
// timeout): R13 (f32x2, verified 831us) + B weight-traffic cut (3 v-groups
// instead of 5) + pipelined slice counter.
// Shapes: N=32, C=64, T=300, V=25, K=3, H=4, DK=DV=16. 9600 slices.

#define NTH 512
#define GRID 152
#define NSLICE 9600
#define CC 64
#define VV 25
#define TT 300

typedef unsigned long long u64;

__device__ __forceinline__ u64 fma2(u64 a, u64 b, u64 c) {
    u64 d; asm("fma.rn.f32x2 %0, %1, %2, %3;" : "=l"(d) : "l"(a), "l"(b), "l"(c));
    return d;
}
__device__ __forceinline__ u64 add2(u64 a, u64 b) {
    u64 d; asm("add.rn.f32x2 %0, %1, %2;" : "=l"(d) : "l"(a), "l"(b));
    return d;
}
__device__ __forceinline__ u64 pack2(float v) {
    u64 d; asm("mov.b64 %0, {%1, %1};" : "=l"(d) : "f"(v));
    return d;
}
__device__ __forceinline__ float2 unpk2(u64 d) {
    float2 f; asm("mov.b64 {%0, %1}, %2;" : "=f"(f.x), "=f"(f.y) : "l"(d));
    return f;
}

__device__ int g_counter;

__global__ void reset_counter_kernel() { g_counter = 0; }

constexpr int SW_S = 388;
constexpr int FA_S = 68;
constexpr int GO_S = 388;
constexpr int AW   = 28;   // padded stride for A / fcA / xoT rows
constexpr int FCT_S = 68;  // sfcT row stride

constexpr int OFF_SW  = 0;                       // 64*388 = 24832
constexpr int OFF_SA  = OFF_SW + 64*SW_S;        // 2100
constexpr int OFF_SFC = OFF_SA + 3*VV*AW;        // sfcT: 64*68 = 4352
constexpr int OFF_SC1 = OFF_SFC + 64*FCT_S;
constexpr int OFF_SH1 = OFF_SC1 + 64;
constexpr int OFF_SC2 = OFF_SH1 + 64;
constexpr int OFF_SH2 = OFF_SC2 + 64;
constexpr int OFF_LNG = OFF_SH2 + 64;
constexpr int OFF_LNB = OFF_LNG + 64;
constexpr int OFF_CB  = OFF_LNB + 64;            // 192
constexpr int OFF_FA  = OFF_CB + 192;            // 25*68
constexpr int OFF_QN  = OFF_FA + VV*FA_S;        // 25*68
constexpr int OFF_GO  = OFF_QN + VV*FA_S;        // 25*388
constexpr int OFF_ATT = OFF_GO + VV*GO_S;        // 2500
constexpr int OFF_XOT = OFF_ATT + 2500;          // xoT[e][v]: 64*28 = 1792
constexpr int OFF_FCA = OFF_XOT + 64*AW;         // fcA[c][v]: 64*28 = 1792
constexpr int SMEM_FLOATS = OFF_FCA + 64*AW;     // 51044 floats = 204176 B

__global__ void __launch_bounds__(NTH, 1)
gcn_kernel(const float* __restrict__ x,      const float* __restrict__ A,
           const float* __restrict__ bn1g,   const float* __restrict__ bn1b,
           const float* __restrict__ bn1m,   const float* __restrict__ bn1v,
           const float* __restrict__ conv_w, const float* __restrict__ conv_b,
           const float* __restrict__ ln_g,   const float* __restrict__ ln_b,
           const float* __restrict__ wq,     const float* __restrict__ wk,
           const float* __restrict__ wv,     const float* __restrict__ fc_w,
           const float* __restrict__ gatep,
           const float* __restrict__ bn2g,   const float* __restrict__ bn2b,
           const float* __restrict__ bn2m,   const float* __restrict__ bn2v,
           float* __restrict__ out)
{
    extern __shared__ float sm[];
    float* sW   = sm + OFF_SW;
    float* sA   = sm + OFF_SA;
    float* sfcT = sm + OFF_SFC;
    float* sc1 = sm + OFF_SC1; float* sh1 = sm + OFF_SH1;
    float* sc2 = sm + OFF_SC2; float* sh2 = sm + OFF_SH2;
    float* lng = sm + OFF_LNG; float* lnb = sm + OFF_LNB;
    float* scb = sm + OFF_CB;
    float* fa  = sm + OFF_FA;
    float* qn  = sm + OFF_QN;
    float* go  = sm + OFF_GO;
    float* att = sm + OFF_ATT;
    float* xoT = sm + OFF_XOT;
    float* fcA = sm + OFF_FCA;

    const int tid = threadIdx.x;
    const float gate = __ldg(gatep);

    // ---- one-time weight staging ----
    for (int i = tid; i < 192*64; i += NTH) {
        int o = i >> 6, c = i & 63;
        sW[c*SW_S + o] = conv_w[i];
    }
    for (int i = tid; i < 4096; i += NTH) {
        int c = i >> 6, d = i & 63;
        sW[c*SW_S + 192 + d] = wk[i];
        sW[c*SW_S + 256 + d] = wv[i];
        sW[c*SW_S + 320 + d] = wq[i];
        sfcT[c*FCT_S + d] = fc_w[i];    // sfcT[e][c] = fc_w[e*64+c]
    }
    for (int i = tid; i < 3*VV*AW; i += NTH) {
        int kv = i / AW, w = i - kv * AW;
        sA[i] = (w < VV) ? A[kv * VV + w] : 0.f;
    }
    if (tid < 192) scb[tid] = conv_b[tid];
    if (tid < 64) {
        float s1 = bn1g[tid] * rsqrtf(bn1v[tid] + 1e-5f);
        sc1[tid] = s1; sh1[tid] = bn1b[tid] - bn1m[tid] * s1;
        float s2 = bn2g[tid] * rsqrtf(bn2v[tid] + 1e-5f);
        sc2[tid] = s2; sh2[tid] = bn2b[tid] - bn2m[tid] * s2;
        lng[tid] = ln_g[tid]; lnb[tid] = ln_b[tid];
    }
    __shared__ int s_next;
    if (tid == NTH - 1) s_next = atomicAdd(&g_counter, 1);   // prefetch slice 0
    __syncthreads();

    const int wid = tid >> 5, lane = tid & 31;

    for (;;) {
        // s_next was fetched during the previous iteration (or just above).
        const int slice = s_next;
        if (slice >= NSLICE) break;
        const int n = slice / TT, t = slice - n * TT;

        // ---- Step A: load x slice, BN1, transpose -> fa[v][c] ----
        {
            const float* xs = x + ((long)n * CC * TT + t) * VV;
            for (int i = tid; i < CC * VV; i += NTH) {
                int c = i / VV, v = i - c * VV;
                float val = xs[(long)c * TT * VV + v];
                fa[v * FA_S + c] = fmaf(val, sc1[c], sh1[c]);
            }
        }
        __syncthreads();               // (2)

        // ---- Step A2: LayerNorm per joint -> qn[v][c] ----
        for (int v = wid; v < VV; v += 16) {
            float a0 = fa[v * FA_S + lane];
            float a1 = fa[v * FA_S + 32 + lane];
            float s = a0 + a1, sq = a0 * a0 + a1 * a1;
            #pragma unroll
            for (int off = 16; off; off >>= 1) {
                s  += __shfl_xor_sync(0xffffffffu, s, off);
                sq += __shfl_xor_sync(0xffffffffu, sq, off);
            }
            float mu = s * (1.f / 64.f);
            float var = sq * (1.f / 64.f) - mu * mu;
            float rstd = rsqrtf(var + 1e-6f);
            qn[v * FA_S + lane]      = fmaf((a0 - mu) * rstd, lng[lane],      lnb[lane]);
            qn[v * FA_S + 32 + lane] = fmaf((a1 - mu) * rstd, lng[lane + 32], lnb[lane + 32]);
        }
        __syncthreads();               // (3)

        // ---- Step B: combined GEMM [25 x 64] @ [64 x 384] -> go[v][j] ----
        // 288 threads: vg in {0,1,2} owns 9/9/7 v-rows; jg owns 4 j-cols.
        // Weight re-read factor drops 5x -> 3x.
        if (tid < 288) {
            const int vg = tid / 96;
            const int jg = tid - vg * 96;
            const int j0 = jg * 4;
            const int nrows = (vg == 2) ? 7 : 9;
            const float* opb = ((j0 >= 320) ? qn : fa) + vg * 9 * FA_S;
            u64 acc2[9][2];
            #pragma unroll
            for (int r = 0; r < 9; r++) { acc2[r][0] = 0ull; acc2[r][1] = 0ull; }

            #pragma unroll 2
            for (int c = 0; c < CC; c += 4) {
                // stage 4 weight rows (8 cols-worth as u64 pairs)
                ulonglong2 w2[4];
                #pragma unroll
                for (int i = 0; i < 4; i++)
                    w2[i] = *(const ulonglong2*)(sW + (c + i) * SW_S + j0);
                // stream operand rows (rows >= 25 read harmless adjacent smem;
                // their results are discarded by the guarded store below)
                #pragma unroll
                for (int r = 0; r < 9; r++) {
                    float4 f = *(const float4*)(opb + r * FA_S + c);
                    u64 p0 = pack2(f.x), p1 = pack2(f.y);
                    u64 p2 = pack2(f.z), p3 = pack2(f.w);
                    acc2[r][0] = fma2(p0, w2[0].x, acc2[r][0]);
                    acc2[r][1] = fma2(p0, w2[0].y, acc2[r][1]);
                    acc2[r][0] = fma2(p1, w2[1].x, acc2[r][0]);
                    acc2[r][1] = fma2(p1, w2[1].y, acc2[r][1]);
                    acc2[r][0] = fma2(p2, w2[2].x, acc2[r][0]);
                    acc2[r][1] = fma2(p2, w2[2].y, acc2[r][1]);
                    acc2[r][0] = fma2(p3, w2[3].x, acc2[r][0]);
                    acc2[r][1] = fma2(p3, w2[3].y, acc2[r][1]);
                }
            }
            ulonglong2 b2;
            b2.x = 0ull; b2.y = 0ull;
            if (j0 < 192) b2 = *(const ulonglong2*)(scb + j0);
            #pragma unroll
            for (int r = 0; r < 9; r++) {
                if (r < nrows) {
                    ulonglong2 r2;
                    r2.x = add2(acc2[r][0], b2.x);
                    r2.y = add2(acc2[r][1], b2.y);
                    *(ulonglong2*)(go + (vg * 9 + r) * GO_S + j0) = r2;
                }
            }
        }
        __syncthreads();               // (4)

        // ---- Step C: fixed-branch A contraction (448 threads) ----
        if (tid < 448) {
            const int c = tid / 7, wg = tid - (tid / 7) * 7, w0 = wg * 4;
            u64 acc2[2] = {0ull, 0ull};
            #pragma unroll
            for (int k = 0; k < 3; k++) {
                const float* gp = go + k * 64 + c;
                const float* ap = sA + k * VV * AW + w0;
                #pragma unroll
                for (int v = 0; v < VV; v++) {
                    u64 g2 = pack2(gp[v * GO_S]);
                    ulonglong2 a2 = *(const ulonglong2*)(ap + v * AW);
                    acc2[0] = fma2(g2, a2.x, acc2[0]);
                    acc2[1] = fma2(g2, a2.y, acc2[1]);
                }
            }
            *(ulonglong2*)(fcA + c * AW + w0) = *(ulonglong2*)acc2;
        }
        // ---- Step D1: attention scores; K-fragments in registers (f32x2) ----
        {
            const int h = wid >> 2, r = wid & 3;
            u64 kk[8];
            #pragma unroll
            for (int i = 0; i < 8; i++) kk[i] = 0ull;
            if (lane < VV) {
                const ulonglong2* kp = (const ulonglong2*)(go + lane * GO_S + 192 + h * 16);
                ulonglong2 ka = kp[0], kb = kp[1], kc = kp[2], kd = kp[3];
                kk[0] = ka.x; kk[1] = ka.y; kk[2] = kb.x; kk[3] = kb.y;
                kk[4] = kc.x; kk[5] = kc.y; kk[6] = kd.x; kk[7] = kd.y;
            }
            for (int qi = r; qi < VV; qi += 4) {
                const ulonglong2* qp = (const ulonglong2*)(go + qi * GO_S + 320 + h * 16);
                ulonglong2 qa = qp[0], qb = qp[1], qc = qp[2], qd = qp[3];
                if (lane < VV) {
                    u64 a2 = 0ull;
                    a2 = fma2(qa.x, kk[0], a2); a2 = fma2(qa.y, kk[1], a2);
                    a2 = fma2(qb.x, kk[2], a2); a2 = fma2(qb.y, kk[3], a2);
                    a2 = fma2(qc.x, kk[4], a2); a2 = fma2(qc.y, kk[5], a2);
                    a2 = fma2(qd.x, kk[6], a2); a2 = fma2(qd.y, kk[7], a2);
                    float2 p = unpk2(a2);
                    att[(h * VV + qi) * VV + lane] = (p.x + p.y) * 0.25f;
                }
            }
        }
        __syncthreads();

        // ---- Step D2: softmax over last dim (100 rows of 25) ----
        if (tid < 100) {
            float* row = att + tid * VV;
            float m = row[0];
            #pragma unroll
            for (int j = 1; j < VV; j++) m = fmaxf(m, row[j]);
            float e[VV]; float s = 0.f;
            #pragma unroll
            for (int j = 0; j < VV; j++) { e[j] = __expf(row[j] - m); s += e[j]; }
            float inv = 1.f / s;
            #pragma unroll
            for (int j = 0; j < VV; j++) row[j] = e[j] * inv;
        }
        __syncthreads();

        // ---- Step D3: xoT[e][v] = sum_j attn[h,v,j] * vv[j][e] (f32x2) ----
        {
            const int e0 = wid * 4, h = e0 >> 4;
            if (lane < VV) {
                const float* ap = att + (h * VV + lane) * VV;
                const float* gp = go + 256 + e0;
                u64 acc2[2] = {0ull, 0ull};
                #pragma unroll
                for (int j = 0; j < VV; j++) {
                    u64 a2 = pack2(ap[j]);
                    ulonglong2 v2 = *(const ulonglong2*)(gp + j * GO_S);  // broadcast
                    acc2[0] = fma2(a2, v2.x, acc2[0]);
                    acc2[1] = fma2(a2, v2.y, acc2[1]);
                }
                float2 p01 = unpk2(acc2[0]), p23 = unpk2(acc2[1]);
                xoT[(e0 + 0) * AW + lane] = p01.x;
                xoT[(e0 + 1) * AW + lane] = p01.y;
                xoT[(e0 + 2) * AW + lane] = p23.x;
                xoT[(e0 + 3) * AW + lane] = p23.y;
            }
        }
        // prefetch next slice while D3 results settle (lane 31 of warp 15 is
        // idle in D3/E; write is separated from s_next readers by barriers)
        if (tid == NTH - 1) s_next = atomicAdd(&g_counter, 1);
        __syncthreads();

        // ---- Step E: out = relu(bn2((xo@fc + fa)*gate + fcA)*0.5) (f32x2) ----
        {
            const int c0 = wid * 4;
            if (lane < VV) {
                const int v = lane;
                u64 acc2[2] = {0ull, 0ull};
                const float* xp = xoT + v;
                const float* wp = sfcT + c0;
                #pragma unroll 16
                for (int e = 0; e < CC; e++) {
                    u64 x2 = pack2(xp[e * AW]);
                    ulonglong2 w2 = *(const ulonglong2*)(wp + e * FCT_S);  // broadcast
                    acc2[0] = fma2(x2, w2.x, acc2[0]);
                    acc2[1] = fma2(x2, w2.y, acc2[1]);
                }
                float2 p01 = unpk2(acc2[0]), p23 = unpk2(acc2[1]);
                float accv[4] = {p01.x, p01.y, p23.x, p23.y};
                float4 res = *(const float4*)(fa + v * FA_S + c0);
                float resv[4] = {res.x, res.y, res.z, res.w};
                float* os = out + ((long)n * CC * TT + t) * VV;
                #pragma unroll
                for (int i = 0; i < 4; i++) {
                    float fa_ = accv[i] + resv[i];
                    float f = (fa_ * gate + fcA[(c0 + i) * AW + v]) * 0.5f;
                    float o = fmaf(f, sc2[c0 + i], sh2[c0 + i]);
                    os[(long)(c0 + i) * TT * VV + v] = fmaxf(o, 0.f);
                }
            }
        }
        __syncthreads();   // (1) close slice: fa/xoT/fcA reuse + s_next visible
    }
}

extern "C" void kernel_launch(void* const* d_in, const int* in_sizes, int n_in,
                              void* d_out, int out_size)
{
    (void)in_sizes; (void)n_in; (void)out_size;
    const float* x      = (const float*)d_in[0];
    const float* A      = (const float*)d_in[1];
    const float* bn1g   = (const float*)d_in[2];
    const float* bn1b   = (const float*)d_in[3];
    const float* bn1m   = (const float*)d_in[4];
    const float* bn1v   = (const float*)d_in[5];
    const float* conv_w = (const float*)d_in[6];
    const float* conv_b = (const float*)d_in[7];
    const float* ln_g   = (const float*)d_in[8];
    const float* ln_b   = (const float*)d_in[9];
    const float* wq     = (const float*)d_in[10];
    const float* wk     = (const float*)d_in[11];
    const float* wv     = (const float*)d_in[12];
    const float* fc_w   = (const float*)d_in[13];
    const float* gate   = (const float*)d_in[14];
    const float* bn2g   = (const float*)d_in[15];
    const float* bn2b   = (const float*)d_in[16];
    const float* bn2m   = (const float*)d_in[17];
    const float* bn2v   = (const float*)d_in[18];

    const int smem_bytes = SMEM_FLOATS * 4;
    cudaFuncSetAttribute(gcn_kernel, cudaFuncAttributeMaxDynamicSharedMemorySize, smem_bytes);

    reset_counter_kernel<<<1, 1>>>();
    gcn_kernel<<<GRID, NTH, smem_bytes>>>(
        x, A, bn1g, bn1b, bn1m, bn1v, conv_w, conv_b, ln_g, ln_b,
        wq, wk, wv, fc_w, gate, bn2g, bn2b, bn2m, bn2v, (float*)d_out);
}